// round 6
// baseline (speedup 1.0000x reference)
#include <cuda_runtime.h>
#include <math.h>
#include <cstdint>

// Problem constants
#define Bb   4
#define Tt   4096
#define Dd   1024
#define Hh   16
#define DH   64
#define Mm   (Bb*Tt)          // 16384 rows
#define NELEM (Mm*Dd)         // 16,777,216
#define KCH  32               // k-softmax T-chunks

// ---------------- scratch (device globals; no allocation allowed) -------------
__device__ float g_xn [NELEM];            // k-permuted layout
__device__ float g_q  [NELEM];
__device__ float g_k  [NELEM];
__device__ float g_v  [NELEM];
__device__ float g_h  [NELEM];            // k-permuted layout
__device__ float g_y  [NELEM];
__device__ float g_wt [4*Dd*Dd];          // transposed + tf32-rounded + k-permuted
__device__ float g_ctx[Bb*Hh*DH*DH];
__device__ float g_ss [Bb*2*Dd];
__device__ float g_pm [KCH*Bb*Dd];
__device__ float g_ps [KCH*Bb*Dd];
__device__ float g_m  [Bb*Dd];
__device__ float g_s  [Bb*Dd];

// k-dim permutation within 8-groups: pos(k) = 2*(k%4) + k/4
// so that fragment pairs (k, k+4) are adjacent -> LDS.64 fragment loads.

// ---------------- helpers ----------------
__device__ __forceinline__ float warpSum(float v) {
    #pragma unroll
    for (int o = 16; o > 0; o >>= 1) v += __shfl_xor_sync(0xffffffffu, v, o);
    return v;
}
__device__ __forceinline__ float siluf(float v) { return v / (1.0f + expf(-v)); }

__device__ __forceinline__ float tf32r(float x) {
    uint32_t u;
    asm("cvt.rna.tf32.f32 %0, %1;" : "=r"(u) : "f"(x));
    return __uint_as_float(u);
}

#define CP_ASYNC16(dst, src) \
    asm volatile("cp.async.cg.shared.global [%0], [%1], 16;" :: "r"(dst), "l"(src))
#define CP_COMMIT() asm volatile("cp.async.commit_group;" ::: "memory")
#define CP_WAIT(n)  asm volatile("cp.async.wait_group %0;" :: "n"(n) : "memory")

__device__ __forceinline__ uint32_t smem_u32(const void* p) {
    uint32_t a;
    asm("{ .reg .u64 t; cvta.to.shared.u64 t, %1; cvt.u32.u64 %0, t; }" : "=r"(a) : "l"(p));
    return a;
}

__device__ __forceinline__ void mma_tf32(float* c, uint32_t a0, uint32_t a1, uint32_t a2,
                                         uint32_t a3, uint32_t b0, uint32_t b1) {
    asm volatile(
        "mma.sync.aligned.m16n8k8.row.col.f32.tf32.tf32.f32 "
        "{%0,%1,%2,%3}, {%4,%5,%6,%7}, {%8,%9}, {%0,%1,%2,%3};"
        : "+f"(c[0]), "+f"(c[1]), "+f"(c[2]), "+f"(c[3])
        : "r"(a0), "r"(a1), "r"(a2), "r"(a3), "r"(b0), "r"(b1));
}

// ================= tf32 mma.sync GEMM (k-permuted operands) =================
// C[M,N] = A[M,K] @ Bt[N,K]^T + bias. Tile 128x128x32, 16 warps (4x4, 32x32 each),
// double-buffered cp.async, single sync per iter, 2 CTAs/SM.
#define BM 128
#define BN 128
#define BK 32
#define GSTG 2
#define LDA 40                 // padded row: LDS.64 frag loads conflict-free (phase-wise)
#define ASTG (BM*LDA)          // 5120 floats per A stage
#define BSTG (BN*LDA)
#define NIT  (Dd/BK)           // 32
#define GSMEM (GSTG*(ASTG+BSTG)*4)   // 81920 bytes

template<int EPI>
__global__ void __launch_bounds__(512, 2)
tgemm_k(const float* __restrict__ A, const float* __restrict__ Bt,
        const float* __restrict__ bias, float* __restrict__ C,
        const float* __restrict__ resid, const float* __restrict__ gate)
{
    extern __shared__ float sm[];
    float* smA = sm;
    float* smB = sm + GSTG * ASTG;

    const int tid  = threadIdx.x;
    const int wid  = tid >> 5;
    const int lane = tid & 31;
    const int g    = lane >> 2;
    const int tig  = lane & 3;
    const int wm   = wid >> 2;       // 0..3
    const int wn   = wid & 3;        // 0..3
    const int cRow = blockIdx.y * BM;
    const int cCol = blockIdx.x * BN;

    // producer addressing: 512 threads, 8 chunks(16B)/row; each thread: rows r, r+64
    const int prow = tid >> 3;       // 0..63
    const int pch  = tid & 7;        // 0..7
    const uint32_t sA0 = smem_u32(smA) + (uint32_t)(prow * LDA + pch * 4) * 4;
    const uint32_t sB0 = smem_u32(smB) + (uint32_t)(prow * LDA + pch * 4) * 4;
    const float* gA = A  + (size_t)(cRow + prow) * Dd + pch * 4;
    const float* gB = Bt + (size_t)(cCol + prow) * Dd + pch * 4;

    #define LOAD_STAGE(it) do { \
        int _s = (it) & (GSTG - 1); int _k0 = (it) * BK; \
        uint32_t _sa = sA0 + (uint32_t)(_s * ASTG) * 4; \
        uint32_t _sb = sB0 + (uint32_t)(_s * BSTG) * 4; \
        CP_ASYNC16(_sa,                  gA + _k0); \
        CP_ASYNC16(_sa + 64 * LDA * 4,   gA + (size_t)64 * Dd + _k0); \
        CP_ASYNC16(_sb,                  gB + _k0); \
        CP_ASYNC16(_sb + 64 * LDA * 4,   gB + (size_t)64 * Dd + _k0); \
        CP_COMMIT(); \
    } while (0)

    LOAD_STAGE(0);

    float acc[2][4][4] = {};

    // per-warp fragment base pointers (hoisted)
    const float* aBase = sm + (wm*32 + g) * LDA + 2*tig;            // A rows: +mt*16, +8
    const float* bBase = sm + GSTG*ASTG + (wn*32 + g) * LDA + 2*tig; // B rows: +nt*8

    for (int it = 0; it < NIT; ++it) {
        CP_WAIT(0);
        __syncthreads();              // stage `it` visible; prior compute done everywhere
        if (it + 1 < NIT) LOAD_STAGE(it + 1);

        const int so = (it & (GSTG-1)) * ASTG;   // same offset for A and B regions
        const float* As = aBase + so;
        const float* Bs = bBase + (it & (GSTG-1)) * BSTG;
        #pragma unroll
        for (int ks = 0; ks < 4; ks++) {
            const int kb = ks * 8;
            uint32_t a[2][4];
            #pragma unroll
            for (int mt = 0; mt < 2; mt++) {
                float2 p0 = *(const float2*)(As + mt*16*LDA + kb);
                float2 p1 = *(const float2*)(As + (mt*16+8)*LDA + kb);
                a[mt][0] = __float_as_uint(p0.x);  a[mt][2] = __float_as_uint(p0.y);
                a[mt][1] = __float_as_uint(p1.x);  a[mt][3] = __float_as_uint(p1.y);
            }
            #pragma unroll
            for (int nt = 0; nt < 4; nt++) {
                float2 bb2 = *(const float2*)(Bs + nt*8*LDA + kb);
                uint32_t b0 = __float_as_uint(bb2.x);
                uint32_t b1 = __float_as_uint(bb2.y);
                mma_tf32(acc[0][nt], a[0][0], a[0][1], a[0][2], a[0][3], b0, b1);
                mma_tf32(acc[1][nt], a[1][0], a[1][1], a[1][2], a[1][3], b0, b1);
            }
        }
    }

    // epilogue
    const int bb = cRow >> 12;   // batch index (block fully inside one batch)
    #pragma unroll
    for (int mt = 0; mt < 2; mt++) {
        const int r0 = cRow + wm*32 + mt*16 + g;
        const int r1 = r0 + 8;
        #pragma unroll
        for (int nt = 0; nt < 4; nt++) {
            const int c0 = cCol + wn*32 + nt*8 + tig*2;
            float bx = bias[c0], by = bias[c0+1];
            float2 v0, v1;
            v0.x = acc[mt][nt][0] + bx;  v0.y = acc[mt][nt][1] + by;
            v1.x = acc[mt][nt][2] + bx;  v1.y = acc[mt][nt][3] + by;
            if (EPI == 1) {
                float gx = gate[bb*Dd + c0], gy = gate[bb*Dd + c0 + 1];
                float2 rA = *(const float2*)(resid + (size_t)r0 * Dd + c0);
                float2 rB = *(const float2*)(resid + (size_t)r1 * Dd + c0);
                v0.x = rA.x + gx * v0.x;  v0.y = rA.y + gy * v0.y;
                v1.x = rB.x + gx * v1.x;  v1.y = rB.y + gy * v1.y;
            }
            *(float2*)(C + (size_t)r0 * Dd + c0) = v0;
            *(float2*)(C + (size_t)r1 * Dd + c0) = v1;
        }
    }
    #undef LOAD_STAGE
}

// ---------------- 4 weight transposes in one launch (tf32 round + k-permute) ----------------
__global__ __launch_bounds__(256)
void transpose_round4(const float* __restrict__ W0, const float* __restrict__ W1,
                      const float* __restrict__ W2, const float* __restrict__ W3,
                      float* __restrict__ Wt)
{
    const float* W = (blockIdx.z == 0) ? W0 : (blockIdx.z == 1) ? W1 :
                     (blockIdx.z == 2) ? W2 : W3;
    float* out = Wt + (size_t)blockIdx.z * Dd * Dd;

    __shared__ float t[32][33];
    int x = blockIdx.x * 32 + threadIdx.x;
    int y = blockIdx.y * 32 + threadIdx.y;
    #pragma unroll
    for (int j = 0; j < 32; j += 8)
        t[threadIdx.y + j][threadIdx.x] = W[(size_t)(y + j) * Dd + x];
    __syncthreads();
    int xo = blockIdx.y * 32 + threadIdx.x;   // k index
    int yo = blockIdx.x * 32 + threadIdx.y;   // n index
    int xp = (xo & ~7) | (2 * (xo & 3) + ((xo >> 2) & 1));   // permuted k pos
    #pragma unroll
    for (int j = 0; j < 32; j += 8)
        out[(size_t)(yo + j) * Dd + xp] = tf32r(t[threadIdx.x][threadIdx.y + j]);
}

// ---------------- LayerNorm 1: x -> xn (tf32-rounded, k-permuted store) ----------------
__global__ __launch_bounds__(256)
void ln1_kernel(const float* __restrict__ x, const float* __restrict__ g,
                const float* __restrict__ b, float* __restrict__ out)
{
    const int row = blockIdx.x;
    const float* xr = x + (size_t)row * Dd;
    float4 xv = *(const float4*)(xr + threadIdx.x * 4);
    float s  = xv.x + xv.y + xv.z + xv.w;
    float s2 = xv.x*xv.x + xv.y*xv.y + xv.z*xv.z + xv.w*xv.w;

    __shared__ float sh1[8], sh2[8], bc[2];
    s = warpSum(s); s2 = warpSum(s2);
    int w = threadIdx.x >> 5;
    if ((threadIdx.x & 31) == 0) { sh1[w] = s; sh2[w] = s2; }
    __syncthreads();
    if (threadIdx.x == 0) {
        float a = 0.f, c = 0.f;
        #pragma unroll
        for (int i = 0; i < 8; i++) { a += sh1[i]; c += sh2[i]; }
        bc[0] = a; bc[1] = c;
    }
    __syncthreads();
    float mu  = bc[0] * (1.0f / Dd);
    float var = bc[1] * (1.0f / Dd) - mu * mu;
    float inv = rsqrtf(var + 1e-5f);

    int d = threadIdx.x * 4;
    float4 gv = *(const float4*)(g + d);
    float4 bv = *(const float4*)(b + d);
    float o0 = tf32r((xv.x - mu) * inv * gv.x + bv.x);
    float o1 = tf32r((xv.y - mu) * inv * gv.y + bv.y);
    float o2 = tf32r((xv.z - mu) * inv * gv.z + bv.z);
    float o3 = tf32r((xv.w - mu) * inv * gv.w + bv.w);
    float* op = out + (size_t)row * Dd + (d & ~7) + ((d & 4) ? 1 : 0);
    op[0] = o0; op[2] = o1; op[4] = o2; op[6] = o3;
}

// ---------------- k temporal softmax stats (32 T-chunks) ----------------
__global__ __launch_bounds__(256)
void ksm_part(const float* __restrict__ k, float* __restrict__ pm, float* __restrict__ ps)
{
    int col = blockIdx.x * 256 + threadIdx.x;   // 0..4095
    int b = col >> 10, d = col & 1023;
    int t0 = blockIdx.y * (Tt / KCH);
    const float* p = k + ((size_t)(b * Tt + t0)) * Dd + d;
    float m = -INFINITY, s = 0.0f;
    #pragma unroll 4
    for (int t = 0; t < Tt / KCH; t++) {
        float v = p[(size_t)t * Dd];
        float mn = fmaxf(m, v);
        s = s * expf(m - mn) + expf(v - mn);
        m = mn;
    }
    pm[blockIdx.y * (Bb * Dd) + col] = m;
    ps[blockIdx.y * (Bb * Dd) + col] = s;
}

__global__ __launch_bounds__(256)
void ksm_comb(const float* __restrict__ pm, const float* __restrict__ ps,
              float* __restrict__ gm, float* __restrict__ gs)
{
    int col = blockIdx.x * 256 + threadIdx.x;
    float M = -INFINITY;
    #pragma unroll
    for (int c = 0; c < KCH; c++) M = fmaxf(M, pm[c * (Bb * Dd) + col]);
    float S = 0.0f;
    #pragma unroll
    for (int c = 0; c < KCH; c++)
        S += ps[c * (Bb * Dd) + col] * expf(pm[c * (Bb * Dd) + col] - M);
    gm[col] = M;
    gs[col] = S;
}

// ---------------- zero ctx ----------------
__global__ void zero_kernel(float* __restrict__ p, int n)
{
    int i = blockIdx.x * blockDim.x + threadIdx.x;
    if (i < n) p[i] = 0.0f;
}

// ---------------- ctx with fused k-normalization ----------------
__global__ __launch_bounds__(256)
void ctx_kernel(const float* __restrict__ k, const float* __restrict__ v,
                const float* __restrict__ gm, const float* __restrict__ gs,
                float* __restrict__ ctx)
{
    int bh = blockIdx.x;
    int b = bh >> 4, h = bh & 15;
    __shared__ float ks[64][64];
    __shared__ float vs[64][64];
    __shared__ float gmm[64], gss[64];
    int tr = threadIdx.x >> 4, tc = threadIdx.x & 15;

    if (threadIdx.x < 64) {
        gmm[threadIdx.x] = gm[b * 1024 + h * 64 + threadIdx.x];
        gss[threadIdx.x] = gs[b * 1024 + h * 64 + threadIdx.x];
    }
    __syncthreads();

    float acc[4][4] = {};
    int tbase = blockIdx.y * (Tt / 8);
    for (int tt0 = 0; tt0 < Tt / 8; tt0 += 64) {
        for (int i = threadIdx.x; i < 64 * 16; i += 256) {
            int t  = i >> 4;
            int c4 = (i & 15) * 4;
            size_t off = ((size_t)((b * Tt + tbase + tt0 + t)) * Hh + h) * DH + c4;
            float4 kv = *(const float4*)(k + off);
            kv.x = expf(kv.x - gmm[c4+0]) / gss[c4+0];
            kv.y = expf(kv.y - gmm[c4+1]) / gss[c4+1];
            kv.z = expf(kv.z - gmm[c4+2]) / gss[c4+2];
            kv.w = expf(kv.w - gmm[c4+3]) / gss[c4+3];
            *(float4*)&ks[t][c4] = kv;
            *(float4*)&vs[t][c4] = *(const float4*)(v + off);
        }
        __syncthreads();
        #pragma unroll 8
        for (int t = 0; t < 64; t++) {
            float rk[4], rv[4];
            #pragma unroll
            for (int i = 0; i < 4; i++) rk[i] = ks[t][tr * 4 + i];
            #pragma unroll
            for (int j = 0; j < 4; j++) rv[j] = vs[t][tc * 4 + j];
            #pragma unroll
            for (int i = 0; i < 4; i++)
                #pragma unroll
                for (int j = 0; j < 4; j++)
                    acc[i][j] += rk[i] * rv[j];
        }
        __syncthreads();
    }
    float* c = ctx + (size_t)bh * (DH * DH);
    #pragma unroll
    for (int i = 0; i < 4; i++)
        #pragma unroll
        for (int j = 0; j < 4; j++)
            atomicAdd(&c[(tr * 4 + i) * DH + tc * 4 + j], acc[i][j]);
}

// ---------------- y = softmax(q) @ ctx  (fused feature softmax) ----------------
__global__ __launch_bounds__(256)
void y_kernel(const float* __restrict__ q, const float* __restrict__ ctx,
              float* __restrict__ y)
{
    int bh = blockIdx.x;
    int b = bh >> 4, h = bh & 15;
    __shared__ float cs[DH * DH];
    for (int i = threadIdx.x; i < 1024; i += 256)
        *(float4*)&cs[i * 4] = *(const float4*)(ctx + (size_t)bh * (DH * DH) + i * 4);
    __syncthreads();

    int t = blockIdx.y * 256 + threadIdx.x;
    size_t off = ((size_t)(b * Tt + t) * Hh + h) * DH;
    const float4* qr4 = (const float4*)(q + off);

    float4 qv[16];
    float m = -INFINITY;
    #pragma unroll
    for (int j = 0; j < 16; j++) {
        qv[j] = qr4[j];
        m = fmaxf(m, fmaxf(fmaxf(qv[j].x, qv[j].y), fmaxf(qv[j].z, qv[j].w)));
    }
    float sum = 0.f;
    #pragma unroll
    for (int j = 0; j < 16; j++) {
        qv[j].x = expf(qv[j].x - m); qv[j].y = expf(qv[j].y - m);
        qv[j].z = expf(qv[j].z - m); qv[j].w = expf(qv[j].w - m);
        sum += qv[j].x + qv[j].y + qv[j].z + qv[j].w;
    }
    float sinv = 1.0f / sum;

    float4 acc[16];
    #pragma unroll
    for (int j = 0; j < 16; j++) acc[j] = make_float4(0.f, 0.f, 0.f, 0.f);

    #pragma unroll 4
    for (int j4 = 0; j4 < 16; j4++) {
        int d0 = j4 * 4;
        #pragma unroll
        for (int dd = 0; dd < 4; dd++) {
            float qd = ((dd == 0) ? qv[j4].x : (dd == 1) ? qv[j4].y :
                        (dd == 2) ? qv[j4].z : qv[j4].w) * sinv;
            const float4* crow = (const float4*)(cs + (d0 + dd) * DH);
            #pragma unroll
            for (int j = 0; j < 16; j++) {
                float4 c = crow[j];
                acc[j].x += qd * c.x;
                acc[j].y += qd * c.y;
                acc[j].z += qd * c.z;
                acc[j].w += qd * c.w;
            }
        }
    }
    float4* yr = (float4*)(y + off);
    #pragma unroll
    for (int j = 0; j < 16; j++) yr[j] = acc[j];
}

// ---------------- emb MLP ----------------
__global__ __launch_bounds__(256)
void emb_kernel(const float* __restrict__ emb, const float* __restrict__ W,
                const float* __restrict__ eb, float* __restrict__ ss)
{
    int b = blockIdx.y;
    int n = blockIdx.x * 256 + threadIdx.x;
    __shared__ float es[1024];
    for (int i = threadIdx.x; i < 1024; i += 256) {
        float e = emb[b * 1024 + i];
        es[i] = siluf(e);
    }
    __syncthreads();
    float acc = eb[n];
    #pragma unroll 4
    for (int kk = 0; kk < 1024; kk++)
        acc += es[kk] * W[(size_t)kk * 2048 + n];
    ss[b * 2048 + n] = acc;
}

// ---------------- LN2 + modulation + silu (tf32-rounded, k-permuted store) ----------------
__global__ __launch_bounds__(256)
void ln2_kernel(const float* __restrict__ y, const float* __restrict__ g,
                const float* __restrict__ bb, const float* __restrict__ ss,
                float* __restrict__ h)
{
    const int row = blockIdx.x;
    const int b = row >> 12;
    const float* yr = y + (size_t)row * Dd;
    float4 xv = *(const float4*)(yr + threadIdx.x * 4);
    float s  = xv.x + xv.y + xv.z + xv.w;
    float s2 = xv.x*xv.x + xv.y*xv.y + xv.z*xv.z + xv.w*xv.w;

    __shared__ float sh1[8], sh2[8], bc[2];
    s = warpSum(s); s2 = warpSum(s2);
    int w = threadIdx.x >> 5;
    if ((threadIdx.x & 31) == 0) { sh1[w] = s; sh2[w] = s2; }
    __syncthreads();
    if (threadIdx.x == 0) {
        float a = 0.f, c = 0.f;
        #pragma unroll
        for (int i = 0; i < 8; i++) { a += sh1[i]; c += sh2[i]; }
        bc[0] = a; bc[1] = c;
    }
    __syncthreads();
    float mu  = bc[0] * (1.0f / Dd);
    float var = bc[1] * (1.0f / Dd) - mu * mu;
    float inv = rsqrtf(var + 1e-5f);

    int d = threadIdx.x * 4;
    float4 gv = *(const float4*)(g + d);
    float4 bv = *(const float4*)(bb + d);
    float4 sc = *(const float4*)(ss + b * 2048 + d);
    float4 sf = *(const float4*)(ss + b * 2048 + 1024 + d);
    float o0 = tf32r(siluf(((xv.x - mu) * inv * gv.x + bv.x) * (1.0f + sc.x) + sf.x));
    float o1 = tf32r(siluf(((xv.y - mu) * inv * gv.y + bv.y) * (1.0f + sc.y) + sf.y));
    float o2 = tf32r(siluf(((xv.z - mu) * inv * gv.z + bv.z) * (1.0f + sc.z) + sf.z));
    float o3 = tf32r(siluf(((xv.w - mu) * inv * gv.w + bv.w) * (1.0f + sc.w) + sf.w));
    float* op = h + (size_t)row * Dd + (d & ~7) + ((d & 4) ? 1 : 0);
    op[0] = o0; op[2] = o1; op[4] = o2; op[6] = o3;
}

// ---------------- launch ----------------
extern "C" void kernel_launch(void* const* d_in, const int* in_sizes, int n_in,
                              void* d_out, int out_size)
{
    const float* x        = (const float*)d_in[0];
    const float* emb      = (const float*)d_in[1];
    const float* gate_msa = (const float*)d_in[2];
    const float* norm_g   = (const float*)d_in[3];
    const float* norm_b   = (const float*)d_in[4];
    const float* Wq       = (const float*)d_in[5];
    const float* bq       = (const float*)d_in[6];
    const float* Wk       = (const float*)d_in[7];
    const float* bk       = (const float*)d_in[8];
    const float* Wv       = (const float*)d_in[9];
    const float* bv       = (const float*)d_in[10];
    const float* emb_W    = (const float*)d_in[11];
    const float* emb_b    = (const float*)d_in[12];
    const float* sn_g     = (const float*)d_in[13];
    const float* sn_b     = (const float*)d_in[14];
    const float* out_W    = (const float*)d_in[15];
    const float* out_b    = (const float*)d_in[16];
    float* out = (float*)d_out;

    float *xn, *q, *k, *v, *y, *h, *wt, *ctx, *ss, *pm, *ps, *gm, *gs;
    cudaGetSymbolAddress((void**)&xn,  g_xn);
    cudaGetSymbolAddress((void**)&q,   g_q);
    cudaGetSymbolAddress((void**)&k,   g_k);
    cudaGetSymbolAddress((void**)&v,   g_v);
    cudaGetSymbolAddress((void**)&y,   g_y);
    cudaGetSymbolAddress((void**)&h,   g_h);
    cudaGetSymbolAddress((void**)&wt,  g_wt);
    cudaGetSymbolAddress((void**)&ctx, g_ctx);
    cudaGetSymbolAddress((void**)&ss,  g_ss);
    cudaGetSymbolAddress((void**)&pm,  g_pm);
    cudaGetSymbolAddress((void**)&ps,  g_ps);
    cudaGetSymbolAddress((void**)&gm,  g_m);
    cudaGetSymbolAddress((void**)&gs,  g_s);

    cudaFuncSetAttribute(tgemm_k<0>, cudaFuncAttributeMaxDynamicSharedMemorySize, GSMEM);
    cudaFuncSetAttribute(tgemm_k<1>, cudaFuncAttributeMaxDynamicSharedMemorySize, GSMEM);

    // weight transposes (+ tf32 rounding + k-permute), one launch
    transpose_round4<<<dim3(32, 32, 4), dim3(32, 8)>>>(Wq, Wk, Wv, out_W, wt);

    // 1. LayerNorm (k-permuted out)
    ln1_kernel<<<Mm, 256>>>(x, norm_g, norm_b, xn);

    // 2-4. Q/K/V projections (tf32 mma.sync, 512 thr, 2 CTAs/SM)
    dim3 gg(Dd / 128, Mm / 128);
    tgemm_k<0><<<gg, 512, GSMEM>>>(xn, wt + 0 * Dd * Dd, bq, q, nullptr, nullptr);
    tgemm_k<0><<<gg, 512, GSMEM>>>(xn, wt + 1 * Dd * Dd, bk, k, nullptr, nullptr);
    tgemm_k<0><<<gg, 512, GSMEM>>>(xn, wt + 2 * Dd * Dd, bv, v, nullptr, nullptr);

    // 5-6. k temporal softmax stats
    ksm_part<<<dim3(16, KCH), 256>>>(k, pm, ps);
    ksm_comb<<<16, 256>>>(pm, ps, gm, gs);

    // 7-8. context (k-normalize fused)
    zero_kernel<<<1024, 256>>>(ctx, Bb * Hh * DH * DH);
    ctx_kernel<<<dim3(Bb * Hh, 8), 256>>>(k, v, gm, gs, ctx);

    // 9. y = softmax(q) @ ctx (q softmax fused)
    y_kernel<<<dim3(Bb * Hh, Tt / 256), 256>>>(q, ctx, y);

    // 10. emb MLP
    emb_kernel<<<dim3(8, Bb), 256>>>(emb, emb_W, emb_b, ss);

    // 11. LN2 + modulation + silu (k-permuted out)
    ln2_kernel<<<Mm, 256>>>(y, sn_g, sn_b, ss, h);

    // 12. out projection + residual epilogue
    tgemm_k<1><<<gg, 512, GSMEM>>>(h, wt + 3 * Dd * Dd, out_b, out, x, gate_msa);
}

// round 7
// speedup vs baseline: 1.0446x; 1.0446x over previous
#include <cuda_runtime.h>
#include <math.h>
#include <cstdint>

// Problem constants
#define Bb   4
#define Tt   4096
#define Dd   1024
#define Hh   16
#define DH   64
#define Mm   (Bb*Tt)          // 16384 rows
#define NELEM (Mm*Dd)         // 16,777,216
#define KCH  32               // k-softmax T-chunks

// ---------------- scratch (device globals; no allocation allowed) -------------
__device__ float g_xn [NELEM];            // k-permuted layout
__device__ float g_q  [NELEM];
__device__ float g_k  [NELEM];
__device__ float g_v  [NELEM];
__device__ float g_h  [NELEM];            // k-permuted layout
__device__ float g_y  [NELEM];
__device__ float g_wt [4*Dd*Dd];          // transposed + tf32-rounded + k-permuted (q,k,v,out)
__device__ float g_ctx[Bb*Hh*DH*DH];
__device__ float g_ss [Bb*2*Dd];
__device__ float g_pm [KCH*Bb*Dd];
__device__ float g_ps [KCH*Bb*Dd];
__device__ float g_m  [Bb*Dd];
__device__ float g_s  [Bb*Dd];

// k-dim permutation within 8-groups: pos(k) = 2*(k%4) + k/4
// so that fragment pairs (k, k+4) are adjacent -> LDS.64 fragment loads.

// ---------------- helpers ----------------
__device__ __forceinline__ float warpSum(float v) {
    #pragma unroll
    for (int o = 16; o > 0; o >>= 1) v += __shfl_xor_sync(0xffffffffu, v, o);
    return v;
}
__device__ __forceinline__ float siluf(float v) { return v / (1.0f + expf(-v)); }

__device__ __forceinline__ float tf32r(float x) {
    uint32_t u;
    asm("cvt.rna.tf32.f32 %0, %1;" : "=r"(u) : "f"(x));
    return __uint_as_float(u);
}

#define CP_ASYNC16(dst, src) \
    asm volatile("cp.async.cg.shared.global [%0], [%1], 16;" :: "r"(dst), "l"(src))
#define CP_COMMIT() asm volatile("cp.async.commit_group;" ::: "memory")
#define CP_WAIT(n)  asm volatile("cp.async.wait_group %0;" :: "n"(n) : "memory")

__device__ __forceinline__ uint32_t smem_u32(const void* p) {
    uint32_t a;
    asm("{ .reg .u64 t; cvta.to.shared.u64 t, %1; cvt.u32.u64 %0, t; }" : "=r"(a) : "l"(p));
    return a;
}

__device__ __forceinline__ void lds64(uint32_t addr, uint32_t& r0, uint32_t& r1) {
    asm volatile("ld.shared.v2.b32 {%0,%1}, [%2];" : "=r"(r0), "=r"(r1) : "r"(addr));
}

__device__ __forceinline__ void mma_tf32(float* c, uint32_t a0, uint32_t a1, uint32_t a2,
                                         uint32_t a3, uint32_t b0, uint32_t b1) {
    asm volatile(
        "mma.sync.aligned.m16n8k8.row.col.f32.tf32.tf32.f32 "
        "{%0,%1,%2,%3}, {%4,%5,%6,%7}, {%8,%9}, {%0,%1,%2,%3};"
        : "+f"(c[0]), "+f"(c[1]), "+f"(c[2]), "+f"(c[3])
        : "r"(a0), "r"(a1), "r"(a2), "r"(a3), "r"(b0), "r"(b1));
}

// ================= tf32 mma.sync GEMM (k-permuted operands) =================
// Tile 128x128x32, 8 warps (4x2), warp tile 32x64, double-buffered cp.async,
// single sync per iteration, 2 CTAs/SM.
// MODE 0: fused QKV. Bt has 3072 rows (Wq|Wk|Wv); blockIdx.x in [0,24);
//         output buffer + bias selected by blockIdx.x>>3.
// MODE 1: out projection + residual epilogue; blockIdx.x in [0,8).
#define BM 128
#define BN 128
#define BK 32
#define GSTG 2
#define LDA 40
#define ASTG (BM*LDA)          // 5120 floats per stage (A and B identical)
#define NIT  (Dd/BK)           // 32
#define GSMEM (GSTG*2*ASTG*4)  // 81920 bytes

template<int MODE>
__global__ void __launch_bounds__(256, 2)
tgemm_k(const float* __restrict__ A, const float* __restrict__ Bt,
        const float* __restrict__ bias_q, const float* __restrict__ bias_k,
        const float* __restrict__ bias_v,
        float* __restrict__ Cq, float* __restrict__ Ck, float* __restrict__ Cv,
        const float* __restrict__ resid, const float* __restrict__ gate)
{
    extern __shared__ float sm[];

    const int tid  = threadIdx.x;
    const int wid  = tid >> 5;
    const int lane = tid & 31;
    const int g    = lane >> 2;
    const int tig  = lane & 3;
    const int wm   = wid >> 1;       // 0..3
    const int wn   = wid & 1;        // 0..1
    const int cRow = blockIdx.y * BM;

    // output selection
    const float* bias; float* C; int cCol;
    if (MODE == 0) {
        int sel = blockIdx.x >> 3;
        bias = (sel == 0) ? bias_q : (sel == 1) ? bias_k : bias_v;
        C    = (sel == 0) ? Cq     : (sel == 1) ? Ck     : Cv;
        cCol = (blockIdx.x & 7) * BN;
    } else {
        bias = bias_q; C = Cq; cCol = blockIdx.x * BN;
    }

    // producer addressing: 256 threads, 8 chunks(16B)/row, 32 rows/pass, 4 passes
    const int prow = tid >> 3;       // 0..31
    const int pch  = tid & 7;        // 0..7
    const uint32_t smBase = smem_u32(sm);
    const uint32_t sA0 = smBase + (uint32_t)(prow * LDA + pch * 4) * 4;
    const uint32_t sB0 = sA0 + GSTG * ASTG * 4;
    const float* gA = A  + (size_t)(cRow + prow) * Dd + pch * 4;
    const float* gB = Bt + (size_t)(blockIdx.x * BN + prow) * Dd + pch * 4;

    #define LOAD_STAGE(it) do { \
        int _s = (it) & (GSTG - 1); int _k0 = (it) * BK; \
        uint32_t _sa = sA0 + (uint32_t)(_s * ASTG) * 4; \
        uint32_t _sb = sB0 + (uint32_t)(_s * ASTG) * 4; \
        _Pragma("unroll") \
        for (int _p = 0; _p < 4; _p++) { \
            CP_ASYNC16(_sa + _p * 32 * LDA * 4, gA + (size_t)_p * 32 * Dd + _k0); \
            CP_ASYNC16(_sb + _p * 32 * LDA * 4, gB + (size_t)_p * 32 * Dd + _k0); \
        } \
        CP_COMMIT(); \
    } while (0)

    LOAD_STAGE(0);

    float acc[2][8][4] = {};

    // per-warp fragment base addresses (uint32; all inner offsets are immediates)
    const uint32_t aW = smBase + (uint32_t)((wm*32 + g) * LDA + 2*tig) * 4;
    const uint32_t bW = smBase + (uint32_t)(GSTG*ASTG + (wn*64 + g) * LDA + 2*tig) * 4;

    for (int it = 0; it < NIT; ++it) {
        CP_WAIT(0);
        __syncthreads();              // all compute(it-1) done; stage `it` visible
        if (it + 1 < NIT) LOAD_STAGE(it + 1);

        const uint32_t so = (uint32_t)((it & 1) * ASTG * 4);
        const uint32_t aS = aW + so;
        const uint32_t bS = bW + so;
        #pragma unroll
        for (int ks = 0; ks < 4; ks++) {
            const uint32_t kb = ks * 8 * 4;   // byte offset within row
            uint32_t a[2][4];
            lds64(aS + 0*16*LDA*4 + kb, a[0][0], a[0][2]);
            lds64(aS + 0*16*LDA*4 + 8*LDA*4 + kb, a[0][1], a[0][3]);
            lds64(aS + 1*16*LDA*4 + kb, a[1][0], a[1][2]);
            lds64(aS + 1*16*LDA*4 + 8*LDA*4 + kb, a[1][1], a[1][3]);
            #pragma unroll
            for (int nt = 0; nt < 8; nt++) {
                uint32_t b0, b1;
                lds64(bS + nt*8*LDA*4 + kb, b0, b1);
                mma_tf32(acc[0][nt], a[0][0], a[0][1], a[0][2], a[0][3], b0, b1);
                mma_tf32(acc[1][nt], a[1][0], a[1][1], a[1][2], a[1][3], b0, b1);
            }
        }
    }

    // epilogue
    const int bb = cRow >> 12;   // batch index (block fully inside one batch)
    #pragma unroll
    for (int mt = 0; mt < 2; mt++) {
        const int r0 = cRow + wm*32 + mt*16 + g;
        const int r1 = r0 + 8;
        #pragma unroll
        for (int nt = 0; nt < 8; nt++) {
            const int c0 = cCol + wn*64 + nt*8 + tig*2;
            float bx = bias[c0], by = bias[c0+1];
            float2 v0, v1;
            v0.x = acc[mt][nt][0] + bx;  v0.y = acc[mt][nt][1] + by;
            v1.x = acc[mt][nt][2] + bx;  v1.y = acc[mt][nt][3] + by;
            if (MODE == 1) {
                float gx = gate[bb*Dd + c0], gy = gate[bb*Dd + c0 + 1];
                float2 rA = *(const float2*)(resid + (size_t)r0 * Dd + c0);
                float2 rB = *(const float2*)(resid + (size_t)r1 * Dd + c0);
                v0.x = rA.x + gx * v0.x;  v0.y = rA.y + gy * v0.y;
                v1.x = rB.x + gx * v1.x;  v1.y = rB.y + gy * v1.y;
            }
            *(float2*)(C + (size_t)r0 * Dd + c0) = v0;
            *(float2*)(C + (size_t)r1 * Dd + c0) = v1;
        }
    }
    #undef LOAD_STAGE
}

// ---------------- 4 weight transposes in one launch (tf32 round + k-permute) ----------------
__global__ __launch_bounds__(256)
void transpose_round4(const float* __restrict__ W0, const float* __restrict__ W1,
                      const float* __restrict__ W2, const float* __restrict__ W3,
                      float* __restrict__ Wt)
{
    const float* W = (blockIdx.z == 0) ? W0 : (blockIdx.z == 1) ? W1 :
                     (blockIdx.z == 2) ? W2 : W3;
    float* out = Wt + (size_t)blockIdx.z * Dd * Dd;

    __shared__ float t[32][33];
    int x = blockIdx.x * 32 + threadIdx.x;
    int y = blockIdx.y * 32 + threadIdx.y;
    #pragma unroll
    for (int j = 0; j < 32; j += 8)
        t[threadIdx.y + j][threadIdx.x] = W[(size_t)(y + j) * Dd + x];
    __syncthreads();
    int xo = blockIdx.y * 32 + threadIdx.x;   // k index
    int yo = blockIdx.x * 32 + threadIdx.y;   // n index
    int xp = (xo & ~7) | (2 * (xo & 3) + ((xo >> 2) & 1));   // permuted k pos
    #pragma unroll
    for (int j = 0; j < 32; j += 8)
        out[(size_t)(yo + j) * Dd + xp] = tf32r(t[threadIdx.x][threadIdx.y + j]);
}

// ---------------- LayerNorm 1: x -> xn (tf32-rounded, k-permuted store) ----------------
__global__ __launch_bounds__(256)
void ln1_kernel(const float* __restrict__ x, const float* __restrict__ g,
                const float* __restrict__ b, float* __restrict__ out)
{
    const int row = blockIdx.x;
    const float* xr = x + (size_t)row * Dd;
    float4 xv = *(const float4*)(xr + threadIdx.x * 4);
    float s  = xv.x + xv.y + xv.z + xv.w;
    float s2 = xv.x*xv.x + xv.y*xv.y + xv.z*xv.z + xv.w*xv.w;

    __shared__ float sh1[8], sh2[8], bc[2];
    s = warpSum(s); s2 = warpSum(s2);
    int w = threadIdx.x >> 5;
    if ((threadIdx.x & 31) == 0) { sh1[w] = s; sh2[w] = s2; }
    __syncthreads();
    if (threadIdx.x == 0) {
        float a = 0.f, c = 0.f;
        #pragma unroll
        for (int i = 0; i < 8; i++) { a += sh1[i]; c += sh2[i]; }
        bc[0] = a; bc[1] = c;
    }
    __syncthreads();
    float mu  = bc[0] * (1.0f / Dd);
    float var = bc[1] * (1.0f / Dd) - mu * mu;
    float inv = rsqrtf(var + 1e-5f);

    int d = threadIdx.x * 4;
    float4 gv = *(const float4*)(g + d);
    float4 bv = *(const float4*)(b + d);
    float o0 = tf32r((xv.x - mu) * inv * gv.x + bv.x);
    float o1 = tf32r((xv.y - mu) * inv * gv.y + bv.y);
    float o2 = tf32r((xv.z - mu) * inv * gv.z + bv.z);
    float o3 = tf32r((xv.w - mu) * inv * gv.w + bv.w);
    float* op = out + (size_t)row * Dd + (d & ~7) + ((d & 4) ? 1 : 0);
    op[0] = o0; op[2] = o1; op[4] = o2; op[6] = o3;
}

// ---------------- k temporal softmax stats (32 T-chunks) ----------------
__global__ __launch_bounds__(256)
void ksm_part(const float* __restrict__ k, float* __restrict__ pm, float* __restrict__ ps)
{
    int col = blockIdx.x * 256 + threadIdx.x;   // 0..4095
    int b = col >> 10, d = col & 1023;
    int t0 = blockIdx.y * (Tt / KCH);
    const float* p = k + ((size_t)(b * Tt + t0)) * Dd + d;
    float m = -INFINITY, s = 0.0f;
    #pragma unroll 4
    for (int t = 0; t < Tt / KCH; t++) {
        float v = p[(size_t)t * Dd];
        float mn = fmaxf(m, v);
        s = s * expf(m - mn) + expf(v - mn);
        m = mn;
    }
    pm[blockIdx.y * (Bb * Dd) + col] = m;
    ps[blockIdx.y * (Bb * Dd) + col] = s;
}

__global__ __launch_bounds__(256)
void ksm_comb(const float* __restrict__ pm, const float* __restrict__ ps,
              float* __restrict__ gm, float* __restrict__ gs)
{
    int col = blockIdx.x * 256 + threadIdx.x;
    float M = -INFINITY;
    #pragma unroll
    for (int c = 0; c < KCH; c++) M = fmaxf(M, pm[c * (Bb * Dd) + col]);
    float S = 0.0f;
    #pragma unroll
    for (int c = 0; c < KCH; c++)
        S += ps[c * (Bb * Dd) + col] * expf(pm[c * (Bb * Dd) + col] - M);
    gm[col] = M;
    gs[col] = S;
}

// ---------------- zero ctx ----------------
__global__ void zero_kernel(float* __restrict__ p, int n)
{
    int i = blockIdx.x * blockDim.x + threadIdx.x;
    if (i < n) p[i] = 0.0f;
}

// ---------------- ctx with fused k-normalization ----------------
__global__ __launch_bounds__(256)
void ctx_kernel(const float* __restrict__ k, const float* __restrict__ v,
                const float* __restrict__ gm, const float* __restrict__ gs,
                float* __restrict__ ctx)
{
    int bh = blockIdx.x;
    int b = bh >> 4, h = bh & 15;
    __shared__ float ks[64][64];
    __shared__ float vs[64][64];
    __shared__ float gmm[64], gss[64];
    int tr = threadIdx.x >> 4, tc = threadIdx.x & 15;

    if (threadIdx.x < 64) {
        gmm[threadIdx.x] = gm[b * 1024 + h * 64 + threadIdx.x];
        gss[threadIdx.x] = gs[b * 1024 + h * 64 + threadIdx.x];
    }
    __syncthreads();

    float acc[4][4] = {};
    int tbase = blockIdx.y * (Tt / 8);
    for (int tt0 = 0; tt0 < Tt / 8; tt0 += 64) {
        for (int i = threadIdx.x; i < 64 * 16; i += 256) {
            int t  = i >> 4;
            int c4 = (i & 15) * 4;
            size_t off = ((size_t)((b * Tt + tbase + tt0 + t)) * Hh + h) * DH + c4;
            float4 kv = *(const float4*)(k + off);
            kv.x = expf(kv.x - gmm[c4+0]) / gss[c4+0];
            kv.y = expf(kv.y - gmm[c4+1]) / gss[c4+1];
            kv.z = expf(kv.z - gmm[c4+2]) / gss[c4+2];
            kv.w = expf(kv.w - gmm[c4+3]) / gss[c4+3];
            *(float4*)&ks[t][c4] = kv;
            *(float4*)&vs[t][c4] = *(const float4*)(v + off);
        }
        __syncthreads();
        #pragma unroll 8
        for (int t = 0; t < 64; t++) {
            float rk[4], rv[4];
            #pragma unroll
            for (int i = 0; i < 4; i++) rk[i] = ks[t][tr * 4 + i];
            #pragma unroll
            for (int j = 0; j < 4; j++) rv[j] = vs[t][tc * 4 + j];
            #pragma unroll
            for (int i = 0; i < 4; i++)
                #pragma unroll
                for (int j = 0; j < 4; j++)
                    acc[i][j] += rk[i] * rv[j];
        }
        __syncthreads();
    }
    float* c = ctx + (size_t)bh * (DH * DH);
    #pragma unroll
    for (int i = 0; i < 4; i++)
        #pragma unroll
        for (int j = 0; j < 4; j++)
            atomicAdd(&c[(tr * 4 + i) * DH + tc * 4 + j], acc[i][j]);
}

// ---------------- y = softmax(q) @ ctx  (fused feature softmax) ----------------
__global__ __launch_bounds__(256)
void y_kernel(const float* __restrict__ q, const float* __restrict__ ctx,
              float* __restrict__ y)
{
    int bh = blockIdx.x;
    int b = bh >> 4, h = bh & 15;
    __shared__ float cs[DH * DH];
    for (int i = threadIdx.x; i < 1024; i += 256)
        *(float4*)&cs[i * 4] = *(const float4*)(ctx + (size_t)bh * (DH * DH) + i * 4);
    __syncthreads();

    int t = blockIdx.y * 256 + threadIdx.x;
    size_t off = ((size_t)(b * Tt + t) * Hh + h) * DH;
    const float4* qr4 = (const float4*)(q + off);

    float4 qv[16];
    float m = -INFINITY;
    #pragma unroll
    for (int j = 0; j < 16; j++) {
        qv[j] = qr4[j];
        m = fmaxf(m, fmaxf(fmaxf(qv[j].x, qv[j].y), fmaxf(qv[j].z, qv[j].w)));
    }
    float sum = 0.f;
    #pragma unroll
    for (int j = 0; j < 16; j++) {
        qv[j].x = expf(qv[j].x - m); qv[j].y = expf(qv[j].y - m);
        qv[j].z = expf(qv[j].z - m); qv[j].w = expf(qv[j].w - m);
        sum += qv[j].x + qv[j].y + qv[j].z + qv[j].w;
    }
    float sinv = 1.0f / sum;

    float4 acc[16];
    #pragma unroll
    for (int j = 0; j < 16; j++) acc[j] = make_float4(0.f, 0.f, 0.f, 0.f);

    #pragma unroll 4
    for (int j4 = 0; j4 < 16; j4++) {
        int d0 = j4 * 4;
        #pragma unroll
        for (int dd = 0; dd < 4; dd++) {
            float qd = ((dd == 0) ? qv[j4].x : (dd == 1) ? qv[j4].y :
                        (dd == 2) ? qv[j4].z : qv[j4].w) * sinv;
            const float4* crow = (const float4*)(cs + (d0 + dd) * DH);
            #pragma unroll
            for (int j = 0; j < 16; j++) {
                float4 c = crow[j];
                acc[j].x += qd * c.x;
                acc[j].y += qd * c.y;
                acc[j].z += qd * c.z;
                acc[j].w += qd * c.w;
            }
        }
    }
    float4* yr = (float4*)(y + off);
    #pragma unroll
    for (int j = 0; j < 16; j++) yr[j] = acc[j];
}

// ---------------- emb MLP ----------------
__global__ __launch_bounds__(256)
void emb_kernel(const float* __restrict__ emb, const float* __restrict__ W,
                const float* __restrict__ eb, float* __restrict__ ss)
{
    int b = blockIdx.y;
    int n = blockIdx.x * 256 + threadIdx.x;
    __shared__ float es[1024];
    for (int i = threadIdx.x; i < 1024; i += 256) {
        float e = emb[b * 1024 + i];
        es[i] = siluf(e);
    }
    __syncthreads();
    float acc = eb[n];
    #pragma unroll 4
    for (int kk = 0; kk < 1024; kk++)
        acc += es[kk] * W[(size_t)kk * 2048 + n];
    ss[b * 2048 + n] = acc;
}

// ---------------- LN2 + modulation + silu (tf32-rounded, k-permuted store) ----------------
__global__ __launch_bounds__(256)
void ln2_kernel(const float* __restrict__ y, const float* __restrict__ g,
                const float* __restrict__ bb, const float* __restrict__ ss,
                float* __restrict__ h)
{
    const int row = blockIdx.x;
    const int b = row >> 12;
    const float* yr = y + (size_t)row * Dd;
    float4 xv = *(const float4*)(yr + threadIdx.x * 4);
    float s  = xv.x + xv.y + xv.z + xv.w;
    float s2 = xv.x*xv.x + xv.y*xv.y + xv.z*xv.z + xv.w*xv.w;

    __shared__ float sh1[8], sh2[8], bc[2];
    s = warpSum(s); s2 = warpSum(s2);
    int w = threadIdx.x >> 5;
    if ((threadIdx.x & 31) == 0) { sh1[w] = s; sh2[w] = s2; }
    __syncthreads();
    if (threadIdx.x == 0) {
        float a = 0.f, c = 0.f;
        #pragma unroll
        for (int i = 0; i < 8; i++) { a += sh1[i]; c += sh2[i]; }
        bc[0] = a; bc[1] = c;
    }
    __syncthreads();
    float mu  = bc[0] * (1.0f / Dd);
    float var = bc[1] * (1.0f / Dd) - mu * mu;
    float inv = rsqrtf(var + 1e-5f);

    int d = threadIdx.x * 4;
    float4 gv = *(const float4*)(g + d);
    float4 bv = *(const float4*)(bb + d);
    float4 sc = *(const float4*)(ss + b * 2048 + d);
    float4 sf = *(const float4*)(ss + b * 2048 + 1024 + d);
    float o0 = tf32r(siluf(((xv.x - mu) * inv * gv.x + bv.x) * (1.0f + sc.x) + sf.x));
    float o1 = tf32r(siluf(((xv.y - mu) * inv * gv.y + bv.y) * (1.0f + sc.y) + sf.y));
    float o2 = tf32r(siluf(((xv.z - mu) * inv * gv.z + bv.z) * (1.0f + sc.z) + sf.z));
    float o3 = tf32r(siluf(((xv.w - mu) * inv * gv.w + bv.w) * (1.0f + sc.w) + sf.w));
    float* op = h + (size_t)row * Dd + (d & ~7) + ((d & 4) ? 1 : 0);
    op[0] = o0; op[2] = o1; op[4] = o2; op[6] = o3;
}

// ---------------- launch ----------------
extern "C" void kernel_launch(void* const* d_in, const int* in_sizes, int n_in,
                              void* d_out, int out_size)
{
    const float* x        = (const float*)d_in[0];
    const float* emb      = (const float*)d_in[1];
    const float* gate_msa = (const float*)d_in[2];
    const float* norm_g   = (const float*)d_in[3];
    const float* norm_b   = (const float*)d_in[4];
    const float* Wq       = (const float*)d_in[5];
    const float* bq       = (const float*)d_in[6];
    const float* Wk       = (const float*)d_in[7];
    const float* bk       = (const float*)d_in[8];
    const float* Wv       = (const float*)d_in[9];
    const float* bv       = (const float*)d_in[10];
    const float* emb_W    = (const float*)d_in[11];
    const float* emb_b    = (const float*)d_in[12];
    const float* sn_g     = (const float*)d_in[13];
    const float* sn_b     = (const float*)d_in[14];
    const float* out_W    = (const float*)d_in[15];
    const float* out_b    = (const float*)d_in[16];
    float* out = (float*)d_out;

    float *xn, *q, *k, *v, *y, *h, *wt, *ctx, *ss, *pm, *ps, *gm, *gs;
    cudaGetSymbolAddress((void**)&xn,  g_xn);
    cudaGetSymbolAddress((void**)&q,   g_q);
    cudaGetSymbolAddress((void**)&k,   g_k);
    cudaGetSymbolAddress((void**)&v,   g_v);
    cudaGetSymbolAddress((void**)&y,   g_y);
    cudaGetSymbolAddress((void**)&h,   g_h);
    cudaGetSymbolAddress((void**)&wt,  g_wt);
    cudaGetSymbolAddress((void**)&ctx, g_ctx);
    cudaGetSymbolAddress((void**)&ss,  g_ss);
    cudaGetSymbolAddress((void**)&pm,  g_pm);
    cudaGetSymbolAddress((void**)&ps,  g_ps);
    cudaGetSymbolAddress((void**)&gm,  g_m);
    cudaGetSymbolAddress((void**)&gs,  g_s);

    cudaFuncSetAttribute(tgemm_k<0>, cudaFuncAttributeMaxDynamicSharedMemorySize, GSMEM);
    cudaFuncSetAttribute(tgemm_k<1>, cudaFuncAttributeMaxDynamicSharedMemorySize, GSMEM);

    // weight transposes (+ tf32 rounding + k-permute), one launch
    transpose_round4<<<dim3(32, 32, 4), dim3(32, 8)>>>(Wq, Wk, Wv, out_W, wt);

    // 1. LayerNorm (k-permuted out)
    ln1_kernel<<<Mm, 256>>>(x, norm_g, norm_b, xn);

    // 2. FUSED Q/K/V projection (one launch, N=3072)
    tgemm_k<0><<<dim3(24, Mm / 128), 256, GSMEM>>>(
        xn, wt, bq, bk, bv, q, k, v, nullptr, nullptr);

    // 3-4. k temporal softmax stats
    ksm_part<<<dim3(16, KCH), 256>>>(k, pm, ps);
    ksm_comb<<<16, 256>>>(pm, ps, gm, gs);

    // 5-6. context (k-normalize fused)
    zero_kernel<<<1024, 256>>>(ctx, Bb * Hh * DH * DH);
    ctx_kernel<<<dim3(Bb * Hh, 8), 256>>>(k, v, gm, gs, ctx);

    // 7. y = softmax(q) @ ctx (q softmax fused)
    y_kernel<<<dim3(Bb * Hh, Tt / 256), 256>>>(q, ctx, y);

    // 8. emb MLP
    emb_kernel<<<dim3(8, Bb), 256>>>(emb, emb_W, emb_b, ss);

    // 9. LN2 + modulation + silu (k-permuted out)
    ln2_kernel<<<Mm, 256>>>(y, sn_g, sn_b, ss, h);

    // 10. out projection + residual epilogue
    tgemm_k<1><<<dim3(8, Mm / 128), 256, GSMEM>>>(
        h, wt + 3 * Dd * Dd, out_b, nullptr, nullptr, out, nullptr, nullptr, x, gate_msa);
}

// round 8
// speedup vs baseline: 1.3673x; 1.3089x over previous
#include <cuda_runtime.h>
#include <cuda_bf16.h>
#include <math.h>
#include <cstdint>

// Problem constants
#define Bb   4
#define Tt   4096
#define Dd   1024
#define Hh   16
#define DH   64
#define Mm   (Bb*Tt)          // 16384 rows
#define NELEM (Mm*Dd)         // 16,777,216
#define KCH  32               // k-softmax T-chunks

// ---------------- scratch (device globals; no allocation allowed) -------------
__device__ __nv_bfloat16 g_xnb[NELEM];    // ln1 out, bf16, pair-permuted
__device__ __nv_bfloat16 g_wtb[3*Dd*Dd];  // Wq|Wk|Wv transposed, bf16, pair-permuted
__device__ float g_q  [NELEM];
__device__ float g_k  [NELEM];
__device__ float g_v  [NELEM];
__device__ float g_h  [NELEM];            // ln2 out, fp32, tf32-permuted
__device__ float g_y  [NELEM];
__device__ float g_wt [Dd*Dd];            // out_W transposed + tf32-rounded + permuted
__device__ float g_ctx[Bb*Hh*DH*DH];
__device__ float g_ss [Bb*2*Dd];
__device__ float g_pm [KCH*Bb*Dd];
__device__ float g_ps [KCH*Bb*Dd];
__device__ float g_m  [Bb*Dd];
__device__ float g_s  [Bb*Dd];

// fp32 (tf32 GEMM) k-permutation within 8-groups: pos8(k) = (k&~7) | 2*(k%4)+k/4
// bf16 GEMM pair-permutation within 16-groups:
//   p=(k>>1)&7, slot=2*(p&3)+(p>>2), pos16(k)=(k&~15) | slot*2 | (k&1)

__host__ __device__ __forceinline__ int pos16(int k) {
    int p = (k >> 1) & 7;
    int slot = 2 * (p & 3) + (p >> 2);
    return (k & ~15) | (slot * 2) | (k & 1);
}

// ---------------- helpers ----------------
__device__ __forceinline__ float warpSum(float v) {
    #pragma unroll
    for (int o = 16; o > 0; o >>= 1) v += __shfl_xor_sync(0xffffffffu, v, o);
    return v;
}
__device__ __forceinline__ float siluf(float v) { return v / (1.0f + expf(-v)); }

__device__ __forceinline__ float tf32r(float x) {
    uint32_t u;
    asm("cvt.rna.tf32.f32 %0, %1;" : "=r"(u) : "f"(x));
    return __uint_as_float(u);
}

#define CP_ASYNC16(dst, src) \
    asm volatile("cp.async.cg.shared.global [%0], [%1], 16;" :: "r"(dst), "l"(src))
#define CP_COMMIT() asm volatile("cp.async.commit_group;" ::: "memory")
#define CP_WAIT(n)  asm volatile("cp.async.wait_group %0;" :: "n"(n) : "memory")

__device__ __forceinline__ uint32_t smem_u32(const void* p) {
    uint32_t a;
    asm("{ .reg .u64 t; cvta.to.shared.u64 t, %1; cvt.u32.u64 %0, t; }" : "=r"(a) : "l"(p));
    return a;
}

__device__ __forceinline__ void lds64(uint32_t addr, uint32_t& r0, uint32_t& r1) {
    asm volatile("ld.shared.v2.b32 {%0,%1}, [%2];" : "=r"(r0), "=r"(r1) : "r"(addr));
}

__device__ __forceinline__ void mma_tf32(float* c, uint32_t a0, uint32_t a1, uint32_t a2,
                                         uint32_t a3, uint32_t b0, uint32_t b1) {
    asm volatile(
        "mma.sync.aligned.m16n8k8.row.col.f32.tf32.tf32.f32 "
        "{%0,%1,%2,%3}, {%4,%5,%6,%7}, {%8,%9}, {%0,%1,%2,%3};"
        : "+f"(c[0]), "+f"(c[1]), "+f"(c[2]), "+f"(c[3])
        : "r"(a0), "r"(a1), "r"(a2), "r"(a3), "r"(b0), "r"(b1));
}

__device__ __forceinline__ void mma_bf16(float* c, uint32_t a0, uint32_t a1, uint32_t a2,
                                         uint32_t a3, uint32_t b0, uint32_t b1) {
    asm volatile(
        "mma.sync.aligned.m16n8k16.row.col.f32.bf16.bf16.f32 "
        "{%0,%1,%2,%3}, {%4,%5,%6,%7}, {%8,%9}, {%0,%1,%2,%3};"
        : "+f"(c[0]), "+f"(c[1]), "+f"(c[2]), "+f"(c[3])
        : "r"(a0), "r"(a1), "r"(a2), "r"(a3), "r"(b0), "r"(b1));
}

// ================= bf16 fused QKV GEMM =================
// Tile 128x128x64(bf16), 8 warps (4x2), warp tile 32x64, double-buffered cp.async.
// Bt has 3072 rows (Wq|Wk|Wv); blockIdx.x in [0,24); out buf + bias by blockIdx.x>>3.
#define BM 128
#define BN 128
#define BKB 64                 // bf16 k per tile
#define LDB 80                 // bf16 per row (160 B, same geometry as 40 floats)
#define BSTGB (BM*LDB)         // 10240 bf16 per stage
#define NITB (Dd/BKB)          // 16
#define GSMEM 81920            // 2 stages x (A+B) x 20480 B

__global__ void __launch_bounds__(256, 2)
qkv_gemm(const __nv_bfloat16* __restrict__ A, const __nv_bfloat16* __restrict__ Bt,
         const float* __restrict__ bias_q, const float* __restrict__ bias_k,
         const float* __restrict__ bias_v,
         float* __restrict__ Cq, float* __restrict__ Ck, float* __restrict__ Cv)
{
    extern __shared__ float sm[];

    const int tid  = threadIdx.x;
    const int wid  = tid >> 5;
    const int lane = tid & 31;
    const int g    = lane >> 2;
    const int tig  = lane & 3;
    const int wm   = wid >> 1;
    const int wn   = wid & 1;
    const int cRow = blockIdx.y * BM;

    const int sel = blockIdx.x >> 3;
    const float* bias = (sel == 0) ? bias_q : (sel == 1) ? bias_k : bias_v;
    float* C          = (sel == 0) ? Cq     : (sel == 1) ? Ck     : Cv;
    const int cCol = (blockIdx.x & 7) * BN;

    const int prow = tid >> 3;       // 0..31
    const int pch  = tid & 7;        // 0..7 (16B chunks)
    const uint32_t smBase = smem_u32(sm);
    const uint32_t sA0 = smBase + (uint32_t)(prow * LDB + pch * 8) * 2;
    const uint32_t sB0 = sA0 + 2u * BSTGB * 2;   // after 2 A stages
    const __nv_bfloat16* gA = A  + (size_t)(cRow + prow) * Dd + pch * 8;
    const __nv_bfloat16* gB = Bt + (size_t)(blockIdx.x * BN + prow) * Dd + pch * 8;

    #define LOAD_STAGE(it) do { \
        int _s = (it) & 1; int _k0 = (it) * BKB; \
        uint32_t _sa = sA0 + (uint32_t)(_s * BSTGB) * 2; \
        uint32_t _sb = sB0 + (uint32_t)(_s * BSTGB) * 2; \
        _Pragma("unroll") \
        for (int _p = 0; _p < 4; _p++) { \
            CP_ASYNC16(_sa + _p * 32 * LDB * 2, gA + (size_t)_p * 32 * Dd + _k0); \
            CP_ASYNC16(_sb + _p * 32 * LDB * 2, gB + (size_t)_p * 32 * Dd + _k0); \
        } \
        CP_COMMIT(); \
    } while (0)

    LOAD_STAGE(0);

    float acc[2][8][4] = {};

    const uint32_t aW = smBase + (uint32_t)((wm*32 + g) * LDB) * 2 + tig * 8;
    const uint32_t bW = smBase + (uint32_t)(2 * BSTGB + (wn*64 + g) * LDB) * 2 + tig * 8;

    for (int it = 0; it < NITB; ++it) {
        CP_WAIT(0);
        __syncthreads();
        if (it + 1 < NITB) LOAD_STAGE(it + 1);

        const uint32_t so = (uint32_t)((it & 1) * BSTGB * 2);
        const uint32_t aS = aW + so;
        const uint32_t bS = bW + so;
        #pragma unroll
        for (int ks = 0; ks < 4; ks++) {
            const uint32_t kb = ks * 32;   // 16 bf16 = 32 bytes per k16 block
            uint32_t a[2][4];
            lds64(aS + kb,                 a[0][0], a[0][2]);
            lds64(aS + 8*LDB*2 + kb,       a[0][1], a[0][3]);
            lds64(aS + 16*LDB*2 + kb,      a[1][0], a[1][2]);
            lds64(aS + 24*LDB*2 + kb,      a[1][1], a[1][3]);
            #pragma unroll
            for (int nt = 0; nt < 8; nt++) {
                uint32_t b0, b1;
                lds64(bS + nt*8*LDB*2 + kb, b0, b1);
                mma_bf16(acc[0][nt], a[0][0], a[0][1], a[0][2], a[0][3], b0, b1);
                mma_bf16(acc[1][nt], a[1][0], a[1][1], a[1][2], a[1][3], b0, b1);
            }
        }
    }

    #pragma unroll
    for (int mt = 0; mt < 2; mt++) {
        const int r0 = cRow + wm*32 + mt*16 + g;
        const int r1 = r0 + 8;
        #pragma unroll
        for (int nt = 0; nt < 8; nt++) {
            const int c0 = cCol + wn*64 + nt*8 + tig*2;
            float bx = bias[c0], by = bias[c0+1];
            float2 v0, v1;
            v0.x = acc[mt][nt][0] + bx;  v0.y = acc[mt][nt][1] + by;
            v1.x = acc[mt][nt][2] + bx;  v1.y = acc[mt][nt][3] + by;
            *(float2*)(C + (size_t)r0 * Dd + c0) = v0;
            *(float2*)(C + (size_t)r1 * Dd + c0) = v1;
        }
    }
    #undef LOAD_STAGE
}

// ================= tf32 out-projection GEMM (unchanged core) =================
#define BK 32
#define LDA 40
#define ASTG (BM*LDA)
#define NIT  (Dd/BK)

__global__ void __launch_bounds__(256, 2)
out_gemm(const float* __restrict__ A, const float* __restrict__ Bt,
         const float* __restrict__ bias, float* __restrict__ C,
         const float* __restrict__ resid, const float* __restrict__ gate)
{
    extern __shared__ float sm[];

    const int tid  = threadIdx.x;
    const int wid  = tid >> 5;
    const int lane = tid & 31;
    const int g    = lane >> 2;
    const int tig  = lane & 3;
    const int wm   = wid >> 1;
    const int wn   = wid & 1;
    const int cRow = blockIdx.y * BM;
    const int cCol = blockIdx.x * BN;

    const int prow = tid >> 3;
    const int pch  = tid & 7;
    const uint32_t smBase = smem_u32(sm);
    const uint32_t sA0 = smBase + (uint32_t)(prow * LDA + pch * 4) * 4;
    const uint32_t sB0 = sA0 + 2u * ASTG * 4;
    const float* gA = A  + (size_t)(cRow + prow) * Dd + pch * 4;
    const float* gB = Bt + (size_t)(cCol + prow) * Dd + pch * 4;

    #define LOAD_STAGE(it) do { \
        int _s = (it) & 1; int _k0 = (it) * BK; \
        uint32_t _sa = sA0 + (uint32_t)(_s * ASTG) * 4; \
        uint32_t _sb = sB0 + (uint32_t)(_s * ASTG) * 4; \
        _Pragma("unroll") \
        for (int _p = 0; _p < 4; _p++) { \
            CP_ASYNC16(_sa + _p * 32 * LDA * 4, gA + (size_t)_p * 32 * Dd + _k0); \
            CP_ASYNC16(_sb + _p * 32 * LDA * 4, gB + (size_t)_p * 32 * Dd + _k0); \
        } \
        CP_COMMIT(); \
    } while (0)

    LOAD_STAGE(0);

    float acc[2][8][4] = {};

    const uint32_t aW = smBase + (uint32_t)((wm*32 + g) * LDA + 2*tig) * 4;
    const uint32_t bW = smBase + (uint32_t)(2*ASTG + (wn*64 + g) * LDA + 2*tig) * 4;

    for (int it = 0; it < NIT; ++it) {
        CP_WAIT(0);
        __syncthreads();
        if (it + 1 < NIT) LOAD_STAGE(it + 1);

        const uint32_t so = (uint32_t)((it & 1) * ASTG * 4);
        const uint32_t aS = aW + so;
        const uint32_t bS = bW + so;
        #pragma unroll
        for (int ks = 0; ks < 4; ks++) {
            const uint32_t kb = ks * 8 * 4;
            uint32_t a[2][4];
            lds64(aS + kb,                a[0][0], a[0][2]);
            lds64(aS + 8*LDA*4 + kb,      a[0][1], a[0][3]);
            lds64(aS + 16*LDA*4 + kb,     a[1][0], a[1][2]);
            lds64(aS + 24*LDA*4 + kb,     a[1][1], a[1][3]);
            #pragma unroll
            for (int nt = 0; nt < 8; nt++) {
                uint32_t b0, b1;
                lds64(bS + nt*8*LDA*4 + kb, b0, b1);
                mma_tf32(acc[0][nt], a[0][0], a[0][1], a[0][2], a[0][3], b0, b1);
                mma_tf32(acc[1][nt], a[1][0], a[1][1], a[1][2], a[1][3], b0, b1);
            }
        }
    }

    const int bb = cRow >> 12;
    #pragma unroll
    for (int mt = 0; mt < 2; mt++) {
        const int r0 = cRow + wm*32 + mt*16 + g;
        const int r1 = r0 + 8;
        #pragma unroll
        for (int nt = 0; nt < 8; nt++) {
            const int c0 = cCol + wn*64 + nt*8 + tig*2;
            float bx = bias[c0], by = bias[c0+1];
            float gx = gate[bb*Dd + c0], gy = gate[bb*Dd + c0 + 1];
            float2 rA = *(const float2*)(resid + (size_t)r0 * Dd + c0);
            float2 rB = *(const float2*)(resid + (size_t)r1 * Dd + c0);
            float2 v0, v1;
            v0.x = rA.x + gx * (acc[mt][nt][0] + bx);
            v0.y = rA.y + gy * (acc[mt][nt][1] + by);
            v1.x = rB.x + gx * (acc[mt][nt][2] + bx);
            v1.y = rB.y + gy * (acc[mt][nt][3] + by);
            *(float2*)(C + (size_t)r0 * Dd + c0) = v0;
            *(float2*)(C + (size_t)r1 * Dd + c0) = v1;
        }
    }
    #undef LOAD_STAGE
}

// ---------------- weight transposes: z<3 -> bf16 (pair-permute); z=3 -> tf32 fp32 ----------------
__global__ __launch_bounds__(256)
void transpose_round4(const float* __restrict__ W0, const float* __restrict__ W1,
                      const float* __restrict__ W2, const float* __restrict__ W3,
                      __nv_bfloat16* __restrict__ Wtb, float* __restrict__ Wt)
{
    const float* W = (blockIdx.z == 0) ? W0 : (blockIdx.z == 1) ? W1 :
                     (blockIdx.z == 2) ? W2 : W3;

    __shared__ float t[32][33];
    int x = blockIdx.x * 32 + threadIdx.x;
    int y = blockIdx.y * 32 + threadIdx.y;
    #pragma unroll
    for (int j = 0; j < 32; j += 8)
        t[threadIdx.y + j][threadIdx.x] = W[(size_t)(y + j) * Dd + x];
    __syncthreads();
    int xo = blockIdx.y * 32 + threadIdx.x;   // k index
    int yo = blockIdx.x * 32 + threadIdx.y;   // n index
    if (blockIdx.z < 3) {
        __nv_bfloat16* out = Wtb + (size_t)blockIdx.z * Dd * Dd;
        int xp = pos16(xo);
        #pragma unroll
        for (int j = 0; j < 32; j += 8)
            out[(size_t)(yo + j) * Dd + xp] = __float2bfloat16(t[threadIdx.x][threadIdx.y + j]);
    } else {
        int xp = (xo & ~7) | (2 * (xo & 3) + ((xo >> 2) & 1));
        #pragma unroll
        for (int j = 0; j < 32; j += 8)
            Wt[(size_t)(yo + j) * Dd + xp] = tf32r(t[threadIdx.x][threadIdx.y + j]);
    }
}

// ---------------- LayerNorm 1: x -> xn (bf16, pair-permuted store) ----------------
__global__ __launch_bounds__(256)
void ln1_kernel(const float* __restrict__ x, const float* __restrict__ g,
                const float* __restrict__ b, __nv_bfloat16* __restrict__ out)
{
    const int row = blockIdx.x;
    const float* xr = x + (size_t)row * Dd;
    float4 xv = *(const float4*)(xr + threadIdx.x * 4);
    float s  = xv.x + xv.y + xv.z + xv.w;
    float s2 = xv.x*xv.x + xv.y*xv.y + xv.z*xv.z + xv.w*xv.w;

    __shared__ float sh1[8], sh2[8], bc[2];
    s = warpSum(s); s2 = warpSum(s2);
    int w = threadIdx.x >> 5;
    if ((threadIdx.x & 31) == 0) { sh1[w] = s; sh2[w] = s2; }
    __syncthreads();
    if (threadIdx.x == 0) {
        float a = 0.f, c = 0.f;
        #pragma unroll
        for (int i = 0; i < 8; i++) { a += sh1[i]; c += sh2[i]; }
        bc[0] = a; bc[1] = c;
    }
    __syncthreads();
    float mu  = bc[0] * (1.0f / Dd);
    float var = bc[1] * (1.0f / Dd) - mu * mu;
    float inv = rsqrtf(var + 1e-5f);

    int d = threadIdx.x * 4;
    float4 gv = *(const float4*)(g + d);
    float4 bv = *(const float4*)(b + d);
    float o0 = (xv.x - mu) * inv * gv.x + bv.x;
    float o1 = (xv.y - mu) * inv * gv.y + bv.y;
    float o2 = (xv.z - mu) * inv * gv.z + bv.z;
    float o3 = (xv.w - mu) * inv * gv.w + bv.w;
    __nv_bfloat162 u0 = __float22bfloat162_rn(make_float2(o0, o1));
    __nv_bfloat162 u1 = __float22bfloat162_rn(make_float2(o2, o3));
    __nv_bfloat16* ob = out + (size_t)row * Dd;
    *(__nv_bfloat162*)(ob + pos16(d))     = u0;
    *(__nv_bfloat162*)(ob + pos16(d + 2)) = u1;
}

// ---------------- k temporal softmax stats (32 T-chunks) ----------------
__global__ __launch_bounds__(256)
void ksm_part(const float* __restrict__ k, float* __restrict__ pm, float* __restrict__ ps)
{
    int col = blockIdx.x * 256 + threadIdx.x;
    int b = col >> 10, d = col & 1023;
    int t0 = blockIdx.y * (Tt / KCH);
    const float* p = k + ((size_t)(b * Tt + t0)) * Dd + d;
    float m = -INFINITY, s = 0.0f;
    #pragma unroll 4
    for (int t = 0; t < Tt / KCH; t++) {
        float v = p[(size_t)t * Dd];
        float mn = fmaxf(m, v);
        s = s * expf(m - mn) + expf(v - mn);
        m = mn;
    }
    pm[blockIdx.y * (Bb * Dd) + col] = m;
    ps[blockIdx.y * (Bb * Dd) + col] = s;
}

__global__ __launch_bounds__(256)
void ksm_comb(const float* __restrict__ pm, const float* __restrict__ ps,
              float* __restrict__ gm, float* __restrict__ gs)
{
    int col = blockIdx.x * 256 + threadIdx.x;
    float M = -INFINITY;
    #pragma unroll
    for (int c = 0; c < KCH; c++) M = fmaxf(M, pm[c * (Bb * Dd) + col]);
    float S = 0.0f;
    #pragma unroll
    for (int c = 0; c < KCH; c++)
        S += ps[c * (Bb * Dd) + col] * expf(pm[c * (Bb * Dd) + col] - M);
    gm[col] = M;
    gs[col] = S;
}

// ---------------- zero ctx ----------------
__global__ void zero_kernel(float* __restrict__ p, int n)
{
    int i = blockIdx.x * blockDim.x + threadIdx.x;
    if (i < n) p[i] = 0.0f;
}

// ---------------- ctx with fused k-normalization ----------------
__global__ __launch_bounds__(256)
void ctx_kernel(const float* __restrict__ k, const float* __restrict__ v,
                const float* __restrict__ gm, const float* __restrict__ gs,
                float* __restrict__ ctx)
{
    int bh = blockIdx.x;
    int b = bh >> 4, h = bh & 15;
    __shared__ float ks[64][64];
    __shared__ float vs[64][64];
    __shared__ float gmm[64], gss[64];
    int tr = threadIdx.x >> 4, tc = threadIdx.x & 15;

    if (threadIdx.x < 64) {
        gmm[threadIdx.x] = gm[b * 1024 + h * 64 + threadIdx.x];
        gss[threadIdx.x] = gs[b * 1024 + h * 64 + threadIdx.x];
    }
    __syncthreads();

    float acc[4][4] = {};
    int tbase = blockIdx.y * (Tt / 8);
    for (int tt0 = 0; tt0 < Tt / 8; tt0 += 64) {
        for (int i = threadIdx.x; i < 64 * 16; i += 256) {
            int t  = i >> 4;
            int c4 = (i & 15) * 4;
            size_t off = ((size_t)((b * Tt + tbase + tt0 + t)) * Hh + h) * DH + c4;
            float4 kv = *(const float4*)(k + off);
            kv.x = expf(kv.x - gmm[c4+0]) / gss[c4+0];
            kv.y = expf(kv.y - gmm[c4+1]) / gss[c4+1];
            kv.z = expf(kv.z - gmm[c4+2]) / gss[c4+2];
            kv.w = expf(kv.w - gmm[c4+3]) / gss[c4+3];
            *(float4*)&ks[t][c4] = kv;
            *(float4*)&vs[t][c4] = *(const float4*)(v + off);
        }
        __syncthreads();
        #pragma unroll 8
        for (int t = 0; t < 64; t++) {
            float rk[4], rv[4];
            #pragma unroll
            for (int i = 0; i < 4; i++) rk[i] = ks[t][tr * 4 + i];
            #pragma unroll
            for (int j = 0; j < 4; j++) rv[j] = vs[t][tc * 4 + j];
            #pragma unroll
            for (int i = 0; i < 4; i++)
                #pragma unroll
                for (int j = 0; j < 4; j++)
                    acc[i][j] += rk[i] * rv[j];
        }
        __syncthreads();
    }
    float* c = ctx + (size_t)bh * (DH * DH);
    #pragma unroll
    for (int i = 0; i < 4; i++)
        #pragma unroll
        for (int j = 0; j < 4; j++)
            atomicAdd(&c[(tr * 4 + i) * DH + tc * 4 + j], acc[i][j]);
}

// ---------------- y = softmax(q) @ ctx  (fused feature softmax) ----------------
__global__ __launch_bounds__(256)
void y_kernel(const float* __restrict__ q, const float* __restrict__ ctx,
              float* __restrict__ y)
{
    int bh = blockIdx.x;
    int b = bh >> 4, h = bh & 15;
    __shared__ float cs[DH * DH];
    for (int i = threadIdx.x; i < 1024; i += 256)
        *(float4*)&cs[i * 4] = *(const float4*)(ctx + (size_t)bh * (DH * DH) + i * 4);
    __syncthreads();

    int t = blockIdx.y * 256 + threadIdx.x;
    size_t off = ((size_t)(b * Tt + t) * Hh + h) * DH;
    const float4* qr4 = (const float4*)(q + off);

    float4 qv[16];
    float m = -INFINITY;
    #pragma unroll
    for (int j = 0; j < 16; j++) {
        qv[j] = qr4[j];
        m = fmaxf(m, fmaxf(fmaxf(qv[j].x, qv[j].y), fmaxf(qv[j].z, qv[j].w)));
    }
    float sum = 0.f;
    #pragma unroll
    for (int j = 0; j < 16; j++) {
        qv[j].x = expf(qv[j].x - m); qv[j].y = expf(qv[j].y - m);
        qv[j].z = expf(qv[j].z - m); qv[j].w = expf(qv[j].w - m);
        sum += qv[j].x + qv[j].y + qv[j].z + qv[j].w;
    }
    float sinv = 1.0f / sum;

    float4 acc[16];
    #pragma unroll
    for (int j = 0; j < 16; j++) acc[j] = make_float4(0.f, 0.f, 0.f, 0.f);

    #pragma unroll 4
    for (int j4 = 0; j4 < 16; j4++) {
        int d0 = j4 * 4;
        #pragma unroll
        for (int dd = 0; dd < 4; dd++) {
            float qd = ((dd == 0) ? qv[j4].x : (dd == 1) ? qv[j4].y :
                        (dd == 2) ? qv[j4].z : qv[j4].w) * sinv;
            const float4* crow = (const float4*)(cs + (d0 + dd) * DH);
            #pragma unroll
            for (int j = 0; j < 16; j++) {
                float4 c = crow[j];
                acc[j].x += qd * c.x;
                acc[j].y += qd * c.y;
                acc[j].z += qd * c.z;
                acc[j].w += qd * c.w;
            }
        }
    }
    float4* yr = (float4*)(y + off);
    #pragma unroll
    for (int j = 0; j < 16; j++) yr[j] = acc[j];
}

// ---------------- emb MLP ----------------
__global__ __launch_bounds__(256)
void emb_kernel(const float* __restrict__ emb, const float* __restrict__ W,
                const float* __restrict__ eb, float* __restrict__ ss)
{
    int b = blockIdx.y;
    int n = blockIdx.x * 256 + threadIdx.x;
    __shared__ float es[1024];
    for (int i = threadIdx.x; i < 1024; i += 256) {
        float e = emb[b * 1024 + i];
        es[i] = siluf(e);
    }
    __syncthreads();
    float acc = eb[n];
    #pragma unroll 4
    for (int kk = 0; kk < 1024; kk++)
        acc += es[kk] * W[(size_t)kk * 2048 + n];
    ss[b * 2048 + n] = acc;
}

// ---------------- LN2 + modulation + silu (tf32-rounded, fp32 permuted store) ----------------
__global__ __launch_bounds__(256)
void ln2_kernel(const float* __restrict__ y, const float* __restrict__ g,
                const float* __restrict__ bb, const float* __restrict__ ss,
                float* __restrict__ h)
{
    const int row = blockIdx.x;
    const int b = row >> 12;
    const float* yr = y + (size_t)row * Dd;
    float4 xv = *(const float4*)(yr + threadIdx.x * 4);
    float s  = xv.x + xv.y + xv.z + xv.w;
    float s2 = xv.x*xv.x + xv.y*xv.y + xv.z*xv.z + xv.w*xv.w;

    __shared__ float sh1[8], sh2[8], bc[2];
    s = warpSum(s); s2 = warpSum(s2);
    int w = threadIdx.x >> 5;
    if ((threadIdx.x & 31) == 0) { sh1[w] = s; sh2[w] = s2; }
    __syncthreads();
    if (threadIdx.x == 0) {
        float a = 0.f, c = 0.f;
        #pragma unroll
        for (int i = 0; i < 8; i++) { a += sh1[i]; c += sh2[i]; }
        bc[0] = a; bc[1] = c;
    }
    __syncthreads();
    float mu  = bc[0] * (1.0f / Dd);
    float var = bc[1] * (1.0f / Dd) - mu * mu;
    float inv = rsqrtf(var + 1e-5f);

    int d = threadIdx.x * 4;
    float4 gv = *(const float4*)(g + d);
    float4 bv = *(const float4*)(bb + d);
    float4 sc = *(const float4*)(ss + b * 2048 + d);
    float4 sf = *(const float4*)(ss + b * 2048 + 1024 + d);
    float o0 = tf32r(siluf(((xv.x - mu) * inv * gv.x + bv.x) * (1.0f + sc.x) + sf.x));
    float o1 = tf32r(siluf(((xv.y - mu) * inv * gv.y + bv.y) * (1.0f + sc.y) + sf.y));
    float o2 = tf32r(siluf(((xv.z - mu) * inv * gv.z + bv.z) * (1.0f + sc.z) + sf.z));
    float o3 = tf32r(siluf(((xv.w - mu) * inv * gv.w + bv.w) * (1.0f + sc.w) + sf.w));
    float* op = h + (size_t)row * Dd + (d & ~7) + ((d & 4) ? 1 : 0);
    op[0] = o0; op[2] = o1; op[4] = o2; op[6] = o3;
}

// ---------------- launch ----------------
extern "C" void kernel_launch(void* const* d_in, const int* in_sizes, int n_in,
                              void* d_out, int out_size)
{
    const float* x        = (const float*)d_in[0];
    const float* emb      = (const float*)d_in[1];
    const float* gate_msa = (const float*)d_in[2];
    const float* norm_g   = (const float*)d_in[3];
    const float* norm_b   = (const float*)d_in[4];
    const float* Wq       = (const float*)d_in[5];
    const float* bq       = (const float*)d_in[6];
    const float* Wk       = (const float*)d_in[7];
    const float* bk       = (const float*)d_in[8];
    const float* Wv       = (const float*)d_in[9];
    const float* bv       = (const float*)d_in[10];
    const float* emb_W    = (const float*)d_in[11];
    const float* emb_b    = (const float*)d_in[12];
    const float* sn_g     = (const float*)d_in[13];
    const float* sn_b     = (const float*)d_in[14];
    const float* out_W    = (const float*)d_in[15];
    const float* out_b    = (const float*)d_in[16];
    float* out = (float*)d_out;

    __nv_bfloat16 *xnb, *wtb;
    float *q, *k, *v, *y, *h, *wt, *ctx, *ss, *pm, *ps, *gm, *gs;
    cudaGetSymbolAddress((void**)&xnb, g_xnb);
    cudaGetSymbolAddress((void**)&wtb, g_wtb);
    cudaGetSymbolAddress((void**)&q,   g_q);
    cudaGetSymbolAddress((void**)&k,   g_k);
    cudaGetSymbolAddress((void**)&v,   g_v);
    cudaGetSymbolAddress((void**)&y,   g_y);
    cudaGetSymbolAddress((void**)&h,   g_h);
    cudaGetSymbolAddress((void**)&wt,  g_wt);
    cudaGetSymbolAddress((void**)&ctx, g_ctx);
    cudaGetSymbolAddress((void**)&ss,  g_ss);
    cudaGetSymbolAddress((void**)&pm,  g_pm);
    cudaGetSymbolAddress((void**)&ps,  g_ps);
    cudaGetSymbolAddress((void**)&gm,  g_m);
    cudaGetSymbolAddress((void**)&gs,  g_s);

    cudaFuncSetAttribute(qkv_gemm, cudaFuncAttributeMaxDynamicSharedMemorySize, GSMEM);
    cudaFuncSetAttribute(out_gemm, cudaFuncAttributeMaxDynamicSharedMemorySize, GSMEM);

    // weight transposes (q,k,v -> bf16 permuted; out_W -> tf32 fp32 permuted)
    transpose_round4<<<dim3(32, 32, 4), dim3(32, 8)>>>(Wq, Wk, Wv, out_W, wtb, wt);

    // 1. LayerNorm -> bf16 (pair-permuted)
    ln1_kernel<<<Mm, 256>>>(x, norm_g, norm_b, xnb);

    // 2. FUSED Q/K/V projection (bf16 m16n8k16)
    qkv_gemm<<<dim3(24, Mm / 128), 256, GSMEM>>>(xnb, wtb, bq, bk, bv, q, k, v);

    // 3-4. k temporal softmax stats
    ksm_part<<<dim3(16, KCH), 256>>>(k, pm, ps);
    ksm_comb<<<16, 256>>>(pm, ps, gm, gs);

    // 5-6. context (k-normalize fused)
    zero_kernel<<<1024, 256>>>(ctx, Bb * Hh * DH * DH);
    ctx_kernel<<<dim3(Bb * Hh, 8), 256>>>(k, v, gm, gs, ctx);

    // 7. y = softmax(q) @ ctx (q softmax fused)
    y_kernel<<<dim3(Bb * Hh, Tt / 256), 256>>>(q, ctx, y);

    // 8. emb MLP
    emb_kernel<<<dim3(8, Bb), 256>>>(emb, emb_W, emb_b, ss);

    // 9. LN2 + modulation + silu (fp32 permuted)
    ln2_kernel<<<Mm, 256>>>(y, sn_g, sn_b, ss, h);

    // 10. out projection + residual epilogue (tf32)
    out_gemm<<<dim3(8, Mm / 128), 256, GSMEM>>>(h, wt, out_b, out, x, gate_msa);
}